// round 15
// baseline (speedup 1.0000x reference)
#include <cuda_runtime.h>
#include <cuda_fp16.h>
#include <cstdint>

#define NQ 16384
#define NC 8192
#define CD 256
#define BM 128
#define BN 128
#define NTILES (NC / BN)      // 64
#define NBLK (NQ / BM)        // 128
#define NTHREADS 512

// ---- device scratch ----
__device__ __half g_Qh[NQ * CD];   // fp16 operands, row-major
__device__ __half g_Eh[NC * CD];
__device__ float g_qsq[NQ];
__device__ float g_esq[NC];
__device__ int4  g_cand[NQ];       // top-4 candidate indices per query
__device__ int   g_argmin[NQ];
__device__ float g_loss;

// ---- SMEM layout (bytes) ----
#define QT_STRIDE 528
#define ET_STRIDE 528
#define ET_BYTES  67584               // 128*528, one full K=256 tile
#define SM_E      67584
#define SM_TOTAL  202752              // Q + 2 E buffers

__device__ __forceinline__ uint32_t smem_u32(const void* p) {
    uint32_t a;
    asm("{ .reg .u64 t; cvta.to.shared.u64 t, %1; cvt.u32.u64 %0, t; }" : "=r"(a) : "l"(p));
    return a;
}

__device__ __forceinline__ void cp16(uint32_t dst, const void* src) {
    asm volatile("cp.async.cg.shared.global [%0], [%1], 16;" :: "r"(dst), "l"(src) : "memory");
}
#define CP_COMMIT() asm volatile("cp.async.commit_group;" ::: "memory")
#define CP_WAIT(N)  asm volatile("cp.async.wait_group %0;" :: "n"(N) : "memory")

__device__ __forceinline__ void ldsm4(uint32_t* r, uint32_t addr) {
    asm volatile("ldmatrix.sync.aligned.m8n8.x4.shared.b16 {%0,%1,%2,%3}, [%4];"
                 : "=r"(r[0]), "=r"(r[1]), "=r"(r[2]), "=r"(r[3]) : "r"(addr));
}

__device__ __forceinline__ void mma16816(float* c, const uint32_t* a, uint32_t b0, uint32_t b1) {
    asm volatile(
        "mma.sync.aligned.m16n8k16.row.col.f32.f16.f16.f32 "
        "{%0,%1,%2,%3}, {%4,%5,%6,%7}, {%8,%9}, {%0,%1,%2,%3};"
        : "+f"(c[0]), "+f"(c[1]), "+f"(c[2]), "+f"(c[3])
        : "r"(a[0]), "r"(a[1]), "r"(a[2]), "r"(a[3]), "r"(b0), "r"(b1));
}

// sorted top-4 insert (ascending), (value,index) lexicographic
__device__ __forceinline__ void ins4(float v, int i, float* bv, int* bi) {
    if (v < bv[3] || (v == bv[3] && i < bi[3])) {
        if (v < bv[1] || (v == bv[1] && i < bi[1])) {
            bv[3] = bv[2]; bi[3] = bi[2]; bv[2] = bv[1]; bi[2] = bi[1];
            if (v < bv[0] || (v == bv[0] && i < bi[0])) {
                bv[1] = bv[0]; bi[1] = bi[0]; bv[0] = v; bi[0] = i;
            } else { bv[1] = v; bi[1] = i; }
        } else {
            if (v < bv[2] || (v == bv[2] && i < bi[2])) {
                bv[3] = bv[2]; bi[3] = bi[2]; bv[2] = v; bi[2] = i;
            } else { bv[3] = v; bi[3] = i; }
        }
    }
}

// ---------------------------------------------------------------------------
// Kernel A: fp16 convert (row-major) + fp32 qsq/esq.  One thread per row.
// ---------------------------------------------------------------------------
__global__ void prep_kernel(const float* __restrict__ Q, const float* __restrict__ E) {
    int idx = blockIdx.x * blockDim.x + threadIdx.x;
    if (idx == 0) g_loss = 0.0f;
    if (idx >= NC + NQ) return;

    const float* src;
    __half* d1;
    if (idx < NC) { src = E + (size_t)idx * CD; d1 = g_Eh + (size_t)idx * CD; }
    else { int q = idx - NC; src = Q + (size_t)q * CD; d1 = g_Qh + (size_t)q * CD; }

    float s = 0.0f;
    const float4* s4 = (const float4*)src;
    #pragma unroll 4
    for (int k4 = 0; k4 < CD / 4; ++k4) {
        float4 v = s4[k4];
        s += v.x * v.x + v.y * v.y + v.z * v.z + v.w * v.w;
        int k = k4 * 4;
        *(__half2*)(d1 + k)     = __floats2half2_rn(v.x, v.y);
        *(__half2*)(d1 + k + 2) = __floats2half2_rn(v.z, v.w);
    }
    if (idx < NC) g_esq[idx] = s;
    else          g_qsq[idx - NC] = s;
}

// ---------------------------------------------------------------------------
// Kernel B: single-pass fp16 mma.sync GEMM + fused top-4 candidate search.
// 512 threads (16 warps = 8 wm x 2 wn, warp tile 16x64) for latency hiding.
// ---------------------------------------------------------------------------
__global__ void __launch_bounds__(NTHREADS, 1) argmin_mma_kernel() {
    extern __shared__ char sm[];
    uint32_t base = smem_u32(sm);
    int tid = threadIdx.x;
    int lane = tid & 31;
    int wid = tid >> 5;
    int wm = wid & 7;             // warp M position (16 rows)
    int wn = wid >> 3;            // warp N position (64 cols)
    int mb = blockIdx.x;

    // ---- stage Q tile + first full E tile via cp.async (8 segs each) ----
    {
        #pragma unroll
        for (int j = 0; j < 8; ++j) {
            int s = j * NTHREADS + tid;          // 4096 16B segs
            int r = s >> 5;
            int seg = s & 31;
            const __half* src = g_Qh + ((size_t)(mb * 128 + r) * CD + seg * 8);
            cp16(base + r * QT_STRIDE + seg * 16, src);
        }
        #pragma unroll
        for (int j = 0; j < 8; ++j) {
            int s = j * NTHREADS + tid;
            int r = s >> 5;
            int seg = s & 31;
            const __half* src = g_Eh + ((size_t)r * CD + seg * 8);
            cp16(base + SM_E + r * ET_STRIDE + seg * 16, src);
        }
        CP_COMMIT();
    }

    int g = lane >> 2;
    float qsq_r[2];
    #pragma unroll
    for (int s = 0; s < 2; ++s)
        qsq_r[s] = __ldg(g_qsq + mb * 128 + wm * 16 + g + s * 8);

    uint32_t aQ = base + (uint32_t)(wm * 16 + (lane & 15)) * QT_STRIDE + ((lane >> 4) << 4);
    uint32_t bE0 = base + SM_E + (uint32_t)(wn * 64 + (lane & 15)) * ET_STRIDE + ((lane >> 4) << 4);

    float acc[8][4];
    #pragma unroll
    for (int nf = 0; nf < 8; ++nf)
        #pragma unroll
        for (int u = 0; u < 4; ++u) acc[nf][u] = 0.0f;

    float bv[2][4];
    int   bi[2][4];
    #pragma unroll
    for (int s = 0; s < 2; ++s)
        #pragma unroll
        for (int j = 0; j < 4; ++j) { bv[s][j] = 3.4e38f; bi[s][j] = 0x7FFFFFFF; }

    int cn_base = wn * 64 + 2 * (lane & 3);

    for (int t = 0; t < NTILES; ++t) {
        int buf = t & 1;

        if (t < NTILES - 1) {
            int bufn = (t + 1) & 1;
            #pragma unroll
            for (int j = 0; j < 8; ++j) {
                int s = j * NTHREADS + tid;
                int r = s >> 5;
                int seg = s & 31;
                const __half* src = g_Eh + ((size_t)((t + 1) * 128 + r) * CD + seg * 8);
                cp16(base + SM_E + bufn * ET_BYTES + r * ET_STRIDE + seg * 16, src);
            }
            CP_COMMIT();
            CP_WAIT(1);
        } else {
            CP_WAIT(0);
        }
        __syncthreads();

        uint32_t bE = bE0 + buf * ET_BYTES;
        #pragma unroll
        for (int ks = 0; ks < 16; ++ks) {
            int kb = ks * 32;
            uint32_t ah[4];
            ldsm4(ah, aQ + kb);
            uint32_t bh[4][4];
            #pragma unroll
            for (int np = 0; np < 4; ++np)
                ldsm4(bh[np], bE + np * 16 * ET_STRIDE + kb);
            #pragma unroll
            for (int np = 0; np < 4; ++np) {
                mma16816(acc[np * 2],     ah, bh[np][0], bh[np][2]);
                mma16816(acc[np * 2 + 1], ah, bh[np][1], bh[np][3]);
            }
        }

        // per-tile epilogue: distances + running top-4, ascending col order
        #pragma unroll
        for (int nf = 0; nf < 8; ++nf) {
            int cn = cn_base + nf * 8;
            float2 eq = __ldg((const float2*)(g_esq + t * 128 + cn));
            float* c = acc[nf];
            float s0 = (qsq_r[0] + eq.x) - 2.0f * c[0];
            float s1 = (qsq_r[0] + eq.y) - 2.0f * c[1];
            float s2 = (qsq_r[1] + eq.x) - 2.0f * c[2];
            float s3 = (qsq_r[1] + eq.y) - 2.0f * c[3];
            int gi = t * 128 + cn;
            ins4(s0, gi,     bv[0], bi[0]);
            ins4(s1, gi + 1, bv[0], bi[0]);
            ins4(s2, gi,     bv[1], bi[1]);
            ins4(s3, gi + 1, bv[1], bi[1]);
            c[0] = 0.0f; c[1] = 0.0f; c[2] = 0.0f; c[3] = 0.0f;
        }
        __syncthreads();
    }

    // ---- cross-thread top-4 merge over tc lanes (offsets 1,2) ----
    #pragma unroll
    for (int s = 0; s < 2; ++s) {
        #pragma unroll
        for (int off = 1; off <= 2; off <<= 1) {
            float ov[4]; int oi[4];
            #pragma unroll
            for (int j = 0; j < 4; ++j) {
                ov[j] = __shfl_xor_sync(0xffffffffu, bv[s][j], off);
                oi[j] = __shfl_xor_sync(0xffffffffu, bi[s][j], off);
            }
            #pragma unroll
            for (int j = 0; j < 4; ++j) ins4(ov[j], oi[j], bv[s], bi[s]);
        }
    }
    // ---- cross-wn merge via smem ----
    float* rv = (float*)(sm + SM_E);            // [4][256]
    int*   ri = (int*)(sm + SM_E + 4096);       // [4][256]
    if ((lane & 3) == 0) {
        #pragma unroll
        for (int s = 0; s < 2; ++s) {
            int row = wm * 16 + g + s * 8;
            #pragma unroll
            for (int j = 0; j < 4; ++j) {
                rv[j * 256 + wn * 128 + row] = bv[s][j];
                ri[j * 256 + wn * 128 + row] = bi[s][j];
            }
        }
    }
    __syncthreads();
    if (tid < 128) {
        float v[4]; int ix[4];
        #pragma unroll
        for (int j = 0; j < 4; ++j) { v[j] = rv[j * 256 + tid]; ix[j] = ri[j * 256 + tid]; }
        #pragma unroll
        for (int j = 0; j < 4; ++j)
            ins4(rv[j * 256 + 128 + tid], ri[j * 256 + 128 + tid], v, ix);
        int4 c;
        c.x = ix[0]; c.y = ix[1]; c.z = ix[2]; c.w = ix[3];
        g_cand[mb * 128 + tid] = c;
    }
}

// ---------------------------------------------------------------------------
// Kernel B2: rescore top-4 with bit-exact sequential fp32 FMA (ascending k),
// candidates processed in ascending index order; strict < (first wins ties).
// ---------------------------------------------------------------------------
__global__ void rescore_kernel(const float* __restrict__ Q, const float* __restrict__ E) {
    int q = blockIdx.x * 256 + threadIdx.x;
    int4 c4 = g_cand[q];
    int id[4] = {c4.x, c4.y, c4.z, c4.w};
    #define SW(a, b) { if (id[a] > id[b]) { int t = id[a]; id[a] = id[b]; id[b] = t; } }
    SW(0, 1) SW(2, 3) SW(0, 2) SW(1, 3) SW(1, 2)
    #undef SW

    const float* qp = Q + (size_t)q * CD;
    float qsq = 0.0f;
    #pragma unroll 4
    for (int k = 0; k < CD; ++k) {
        float qk = qp[k];
        qsq = fmaf(qk, qk, qsq);
    }
    float best = 3.4e38f;
    int bidx = -1;
    for (int j = 0; j < 4; ++j) {
        if (j > 0 && id[j] == id[j - 1]) continue;
        const float* e = E + (size_t)id[j] * CD;
        float es = 0.0f, d = 0.0f;
        #pragma unroll 4
        for (int k = 0; k < CD; ++k) {
            float ek = e[k];
            es = fmaf(ek, ek, es);
            d  = fmaf(qp[k], ek, d);
        }
        float s = (qsq + es) - 2.0f * d;
        if (s < best) { best = s; bidx = id[j]; }
    }
    g_argmin[q] = bidx;
}

// ---------------------------------------------------------------------------
// Kernel C: gather quantized + index output + loss sum
// ---------------------------------------------------------------------------
__global__ void gather_kernel(const float* __restrict__ Q, const float* __restrict__ E,
                              float* __restrict__ out) {
    int q = blockIdx.x * 4 + (threadIdx.x >> 6);
    int lane = threadIdx.x & 63;
    int idx = g_argmin[q];

    float4 qv = ((const float4*)Q)[q * (CD / 4) + lane];
    float4 ev = ((const float4*)E)[(size_t)idx * (CD / 4) + lane];

    float dx = ev.x - qv.x, dy = ev.y - qv.y, dz = ev.z - qv.z, dw = ev.w - qv.w;
    float4 o;
    o.x = qv.x + dx; o.y = qv.y + dy; o.z = qv.z + dz; o.w = qv.w + dw;
    ((float4*)(out + NQ))[q * (CD / 4) + lane] = o;
    if (lane == 0) out[q] = (float)idx;

    float d2 = dx * dx + dy * dy + dz * dz + dw * dw;
    #pragma unroll
    for (int off = 16; off > 0; off >>= 1)
        d2 += __shfl_down_sync(0xffffffffu, d2, off);

    __shared__ float ws[8];
    int w = threadIdx.x >> 5;
    if ((threadIdx.x & 31) == 0) ws[w] = d2;
    __syncthreads();
    if (threadIdx.x == 0) {
        float s = 0.0f;
        #pragma unroll
        for (int i = 0; i < 8; ++i) s += ws[i];
        atomicAdd(&g_loss, s);
    }
}

__global__ void loss_kernel(float* __restrict__ out) {
    out[NQ + NQ * CD] = 1.25f * g_loss * (1.0f / (float)(NQ * CD));
}

// ---------------------------------------------------------------------------
extern "C" void kernel_launch(void* const* d_in, const int* in_sizes, int n_in,
                              void* d_out, int out_size) {
    const float* Q = (const float*)d_in[0];
    const float* E = (const float*)d_in[1];
    if (n_in >= 2 && in_sizes[0] == NC * CD && in_sizes[1] == NQ * CD) {
        const float* t = Q; Q = E; E = t;
    }
    float* out = (float*)d_out;

    cudaFuncSetAttribute(argmin_mma_kernel, cudaFuncAttributeMaxDynamicSharedMemorySize,
                         SM_TOTAL);

    prep_kernel<<<(NC + NQ) / 256, 256>>>(Q, E);
    argmin_mma_kernel<<<NBLK, NTHREADS, SM_TOTAL>>>();
    rescore_kernel<<<NQ / 256, 256>>>(Q, E);
    gather_kernel<<<NQ / 4, 256>>>(Q, E, out);
    loss_kernel<<<1, 1>>>(out);
}

// round 16
// speedup vs baseline: 1.1998x; 1.1998x over previous
#include <cuda_runtime.h>
#include <cuda_fp16.h>
#include <cstdint>

#define NQ 16384
#define NC 8192
#define CD 256
#define BM 128
#define BN 128
#define NHALF 2
#define NC_H (NC / NHALF)         // 4096 codes per half
#define NTILES_H (NC_H / BN)      // 32 tiles per half
#define NBLK (NQ / BM * NHALF)    // 256 blocks
#define NIT (NTILES_H * 4)        // 128 chunk-iterations

// ---- device scratch ----
__device__ __half g_Qh[NQ * CD];
__device__ __half g_Eh[NC * CD];
__device__ float g_qsq[NQ];
__device__ float g_esq[NC];
__device__ int4  g_cand[NHALF * NQ];   // top-4 per half per query
__device__ int   g_argmin[NQ];
__device__ float g_loss;

// ---- SMEM layout (bytes): R13 k-chunked layout, 102 KB -> 2 blocks/SM ----
#define QT_STRIDE 528
#define ET_STRIDE 144
#define ET_BYTES  18432               // 128*144 (one 64-k chunk)
#define SM_E      67584
#define SM_TOTAL  104448

__device__ __forceinline__ uint32_t smem_u32(const void* p) {
    uint32_t a;
    asm("{ .reg .u64 t; cvta.to.shared.u64 t, %1; cvt.u32.u64 %0, t; }" : "=r"(a) : "l"(p));
    return a;
}

__device__ __forceinline__ void cp16(uint32_t dst, const void* src) {
    asm volatile("cp.async.cg.shared.global [%0], [%1], 16;" :: "r"(dst), "l"(src) : "memory");
}
#define CP_COMMIT() asm volatile("cp.async.commit_group;" ::: "memory")
#define CP_WAIT(N)  asm volatile("cp.async.wait_group %0;" :: "n"(N) : "memory")

__device__ __forceinline__ void ldsm4(uint32_t* r, uint32_t addr) {
    asm volatile("ldmatrix.sync.aligned.m8n8.x4.shared.b16 {%0,%1,%2,%3}, [%4];"
                 : "=r"(r[0]), "=r"(r[1]), "=r"(r[2]), "=r"(r[3]) : "r"(addr));
}

__device__ __forceinline__ void mma16816(float* c, const uint32_t* a, uint32_t b0, uint32_t b1) {
    asm volatile(
        "mma.sync.aligned.m16n8k16.row.col.f32.f16.f16.f32 "
        "{%0,%1,%2,%3}, {%4,%5,%6,%7}, {%8,%9}, {%0,%1,%2,%3};"
        : "+f"(c[0]), "+f"(c[1]), "+f"(c[2]), "+f"(c[3])
        : "r"(a[0]), "r"(a[1]), "r"(a[2]), "r"(a[3]), "r"(b0), "r"(b1));
}

// sorted top-4 insert (ascending), (value,index) lexicographic
__device__ __forceinline__ void ins4(float v, int i, float* bv, int* bi) {
    if (v < bv[3] || (v == bv[3] && i < bi[3])) {
        if (v < bv[1] || (v == bv[1] && i < bi[1])) {
            bv[3] = bv[2]; bi[3] = bi[2]; bv[2] = bv[1]; bi[2] = bi[1];
            if (v < bv[0] || (v == bv[0] && i < bi[0])) {
                bv[1] = bv[0]; bi[1] = bi[0]; bv[0] = v; bi[0] = i;
            } else { bv[1] = v; bi[1] = i; }
        } else {
            if (v < bv[2] || (v == bv[2] && i < bi[2])) {
                bv[3] = bv[2]; bi[3] = bi[2]; bv[2] = v; bi[2] = i;
            } else { bv[3] = v; bi[3] = i; }
        }
    }
}

// ---------------------------------------------------------------------------
// Kernel A: fp16 convert (row-major) + fp32 qsq/esq.  One thread per row.
// ---------------------------------------------------------------------------
__global__ void prep_kernel(const float* __restrict__ Q, const float* __restrict__ E) {
    int idx = blockIdx.x * blockDim.x + threadIdx.x;
    if (idx == 0) g_loss = 0.0f;
    if (idx >= NC + NQ) return;

    const float* src;
    __half* d1;
    if (idx < NC) { src = E + (size_t)idx * CD; d1 = g_Eh + (size_t)idx * CD; }
    else { int q = idx - NC; src = Q + (size_t)q * CD; d1 = g_Qh + (size_t)q * CD; }

    float s = 0.0f;
    const float4* s4 = (const float4*)src;
    #pragma unroll 4
    for (int k4 = 0; k4 < CD / 4; ++k4) {
        float4 v = s4[k4];
        s += v.x * v.x + v.y * v.y + v.z * v.z + v.w * v.w;
        int k = k4 * 4;
        *(__half2*)(d1 + k)     = __floats2half2_rn(v.x, v.y);
        *(__half2*)(d1 + k + 2) = __floats2half2_rn(v.z, v.w);
    }
    if (idx < NC) g_esq[idx] = s;
    else          g_qsq[idx - NC] = s;
}

// ---------------------------------------------------------------------------
// Kernel B: fp16 mma.sync GEMM + fused top-4 search.  256 blocks =
// 128 M-blocks x 2 code-halves; 2 blocks/SM for cross-block latency hiding.
// ---------------------------------------------------------------------------
__global__ void __launch_bounds__(256, 2) argmin_mma_kernel() {
    extern __shared__ char sm[];
    uint32_t base = smem_u32(sm);
    int tid = threadIdx.x;
    int lane = tid & 31;
    int wm = (tid >> 5) & 3;      // warp M position (32 rows)
    int wn = tid >> 7;            // warp N position (64 cols)
    int mb = blockIdx.x >> 1;
    int nh = blockIdx.x & 1;
    int ebase = nh * NC_H;        // first code row of this half

    // ---- stage Q tile + first E chunk via cp.async ----
    {
        #pragma unroll
        for (int j = 0; j < 16; ++j) {
            int s = j * 256 + tid;          // 4096 16B segs
            int r = s >> 5;
            int seg = s & 31;
            const __half* src = g_Qh + ((size_t)(mb * 128 + r) * CD + seg * 8);
            cp16(base + r * QT_STRIDE + seg * 16, src);
        }
        #pragma unroll
        for (int j = 0; j < 4; ++j) {
            int idx = j * 256 + tid;
            int row = idx >> 3, sg = idx & 7;
            const __half* src = g_Eh + ((size_t)(ebase + row) * CD + sg * 8);
            cp16(base + SM_E + row * ET_STRIDE + sg * 16, src);
        }
        CP_COMMIT();
    }

    int g = lane >> 2;
    float qsq_r[4];
    #pragma unroll
    for (int s = 0; s < 4; ++s)
        qsq_r[s] = __ldg(g_qsq + mb * 128 + wm * 32 + g + s * 8);

    uint32_t aQ = base + (uint32_t)(wm * 32 + (lane & 15)) * QT_STRIDE + ((lane >> 4) << 4);
    uint32_t bE0 = base + SM_E + (uint32_t)(wn * 64 + (lane & 15)) * ET_STRIDE + ((lane >> 4) << 4);

    float acc[2][8][4];
    #pragma unroll
    for (int mf = 0; mf < 2; ++mf)
        #pragma unroll
        for (int nf = 0; nf < 8; ++nf)
            #pragma unroll
            for (int u = 0; u < 4; ++u) acc[mf][nf][u] = 0.0f;

    float bv[4][4];
    int   bi[4][4];
    #pragma unroll
    for (int s = 0; s < 4; ++s)
        #pragma unroll
        for (int j = 0; j < 4; ++j) { bv[s][j] = 3.4e38f; bi[s][j] = 0x7FFFFFFF; }

    int cn_base = wn * 64 + 2 * (lane & 3);

    for (int it = 0; it < NIT; ++it) {
        int t = it >> 2, kc = it & 3, buf = it & 1;

        if (it < NIT - 1) {
            int nit = it + 1, tn = nit >> 2, kcn = nit & 3, bufn = nit & 1;
            #pragma unroll
            for (int j = 0; j < 4; ++j) {
                int idx = j * 256 + tid;
                int row = idx >> 3, sg = idx & 7;
                const __half* src = g_Eh +
                    ((size_t)(ebase + tn * 128 + row) * CD + kcn * 64 + sg * 8);
                cp16(base + SM_E + bufn * ET_BYTES + row * ET_STRIDE + sg * 16, src);
            }
            CP_COMMIT();
            CP_WAIT(1);
        } else {
            CP_WAIT(0);
        }
        __syncthreads();

        uint32_t bE = bE0 + buf * ET_BYTES;
        #pragma unroll
        for (int ks = 0; ks < 4; ++ks) {
            int kb = kc * 128 + ks * 32;
            uint32_t ah[2][4];
            ldsm4(ah[0], aQ + kb);
            ldsm4(ah[1], aQ + 16 * QT_STRIDE + kb);
            uint32_t bh[4][4];
            #pragma unroll
            for (int np = 0; np < 4; ++np)
                ldsm4(bh[np], bE + np * 16 * ET_STRIDE + ks * 32);
            #pragma unroll
            for (int mf = 0; mf < 2; ++mf) {
                #pragma unroll
                for (int np = 0; np < 4; ++np) {
                    mma16816(acc[mf][np * 2],     ah[mf], bh[np][0], bh[np][2]);
                    mma16816(acc[mf][np * 2 + 1], ah[mf], bh[np][1], bh[np][3]);
                }
            }
        }

        if (kc == 3) {
            #pragma unroll
            for (int nf = 0; nf < 8; ++nf) {
                int cn = cn_base + nf * 8;
                float2 eq = __ldg((const float2*)(g_esq + ebase + t * 128 + cn));
                #pragma unroll
                for (int mf = 0; mf < 2; ++mf) {
                    float* c = acc[mf][nf];
                    float s0 = (qsq_r[mf * 2]     + eq.x) - 2.0f * c[0];
                    float s1 = (qsq_r[mf * 2]     + eq.y) - 2.0f * c[1];
                    float s2 = (qsq_r[mf * 2 + 1] + eq.x) - 2.0f * c[2];
                    float s3 = (qsq_r[mf * 2 + 1] + eq.y) - 2.0f * c[3];
                    int gi = ebase + t * 128 + cn;
                    ins4(s0, gi,     bv[mf * 2],     bi[mf * 2]);
                    ins4(s1, gi + 1, bv[mf * 2],     bi[mf * 2]);
                    ins4(s2, gi,     bv[mf * 2 + 1], bi[mf * 2 + 1]);
                    ins4(s3, gi + 1, bv[mf * 2 + 1], bi[mf * 2 + 1]);
                    c[0] = 0.0f; c[1] = 0.0f; c[2] = 0.0f; c[3] = 0.0f;
                }
            }
        }
        __syncthreads();
    }

    // ---- cross-thread top-4 merge over tc lanes (offsets 1,2) ----
    #pragma unroll
    for (int s = 0; s < 4; ++s) {
        #pragma unroll
        for (int off = 1; off <= 2; off <<= 1) {
            float ov[4]; int oi[4];
            #pragma unroll
            for (int j = 0; j < 4; ++j) {
                ov[j] = __shfl_xor_sync(0xffffffffu, bv[s][j], off);
                oi[j] = __shfl_xor_sync(0xffffffffu, bi[s][j], off);
            }
            #pragma unroll
            for (int j = 0; j < 4; ++j) ins4(ov[j], oi[j], bv[s], bi[s]);
        }
    }
    // ---- cross-wn merge via smem ----
    float* rv = (float*)(sm + SM_E);            // [4][256]
    int*   ri = (int*)(sm + SM_E + 4096);       // [4][256]
    if ((lane & 3) == 0) {
        #pragma unroll
        for (int s = 0; s < 4; ++s) {
            int row = wm * 32 + g + s * 8;
            #pragma unroll
            for (int j = 0; j < 4; ++j) {
                rv[j * 256 + wn * 128 + row] = bv[s][j];
                ri[j * 256 + wn * 128 + row] = bi[s][j];
            }
        }
    }
    __syncthreads();
    if (tid < 128) {
        float v[4]; int ix[4];
        #pragma unroll
        for (int j = 0; j < 4; ++j) { v[j] = rv[j * 256 + tid]; ix[j] = ri[j * 256 + tid]; }
        #pragma unroll
        for (int j = 0; j < 4; ++j)
            ins4(rv[j * 256 + 128 + tid], ri[j * 256 + 128 + tid], v, ix);
        int4 c;
        c.x = ix[0]; c.y = ix[1]; c.z = ix[2]; c.w = ix[3];
        g_cand[nh * NQ + mb * 128 + tid] = c;
    }
}

// ---------------------------------------------------------------------------
// Kernel B2: rescore 8 candidates (top-4 from each half) with bit-exact
// sequential fp32 FMA; ascending index order, strict < (first wins ties).
// ---------------------------------------------------------------------------
__global__ void rescore_kernel(const float* __restrict__ Q, const float* __restrict__ E) {
    int q = blockIdx.x * 256 + threadIdx.x;
    int4 c0 = g_cand[q];
    int4 c1 = g_cand[NQ + q];
    int id[8] = {c0.x, c0.y, c0.z, c0.w, c1.x, c1.y, c1.z, c1.w};
    // insertion sort ascending
    #pragma unroll
    for (int a = 1; a < 8; ++a) {
        int v = id[a], b = a - 1;
        while (b >= 0 && id[b] > v) { id[b + 1] = id[b]; --b; }
        id[b + 1] = v;
    }

    const float* qp = Q + (size_t)q * CD;
    float qsq = 0.0f;
    #pragma unroll 4
    for (int k = 0; k < CD; ++k) {
        float qk = qp[k];
        qsq = fmaf(qk, qk, qsq);
    }
    float best = 3.4e38f;
    int bidx = -1;
    for (int j = 0; j < 8; ++j) {
        if (j > 0 && id[j] == id[j - 1]) continue;
        const float* e = E + (size_t)id[j] * CD;
        float es = 0.0f, d = 0.0f;
        #pragma unroll 4
        for (int k = 0; k < CD; ++k) {
            float ek = e[k];
            es = fmaf(ek, ek, es);
            d  = fmaf(qp[k], ek, d);
        }
        float s = (qsq + es) - 2.0f * d;
        if (s < best) { best = s; bidx = id[j]; }
    }
    g_argmin[q] = bidx;
}

// ---------------------------------------------------------------------------
// Kernel C: gather quantized + index output + loss sum
// ---------------------------------------------------------------------------
__global__ void gather_kernel(const float* __restrict__ Q, const float* __restrict__ E,
                              float* __restrict__ out) {
    int q = blockIdx.x * 4 + (threadIdx.x >> 6);
    int lane = threadIdx.x & 63;
    int idx = g_argmin[q];

    float4 qv = ((const float4*)Q)[q * (CD / 4) + lane];
    float4 ev = ((const float4*)E)[(size_t)idx * (CD / 4) + lane];

    float dx = ev.x - qv.x, dy = ev.y - qv.y, dz = ev.z - qv.z, dw = ev.w - qv.w;
    float4 o;
    o.x = qv.x + dx; o.y = qv.y + dy; o.z = qv.z + dz; o.w = qv.w + dw;
    ((float4*)(out + NQ))[q * (CD / 4) + lane] = o;
    if (lane == 0) out[q] = (float)idx;

    float d2 = dx * dx + dy * dy + dz * dz + dw * dw;
    #pragma unroll
    for (int off = 16; off > 0; off >>= 1)
        d2 += __shfl_down_sync(0xffffffffu, d2, off);

    __shared__ float ws[8];
    int w = threadIdx.x >> 5;
    if ((threadIdx.x & 31) == 0) ws[w] = d2;
    __syncthreads();
    if (threadIdx.x == 0) {
        float s = 0.0f;
        #pragma unroll
        for (int i = 0; i < 8; ++i) s += ws[i];
        atomicAdd(&g_loss, s);
    }
}

__global__ void loss_kernel(float* __restrict__ out) {
    out[NQ + NQ * CD] = 1.25f * g_loss * (1.0f / (float)(NQ * CD));
}

// ---------------------------------------------------------------------------
extern "C" void kernel_launch(void* const* d_in, const int* in_sizes, int n_in,
                              void* d_out, int out_size) {
    const float* Q = (const float*)d_in[0];
    const float* E = (const float*)d_in[1];
    if (n_in >= 2 && in_sizes[0] == NC * CD && in_sizes[1] == NQ * CD) {
        const float* t = Q; Q = E; E = t;
    }
    float* out = (float*)d_out;

    cudaFuncSetAttribute(argmin_mma_kernel, cudaFuncAttributeMaxDynamicSharedMemorySize,
                         SM_TOTAL);

    prep_kernel<<<(NC + NQ) / 256, 256>>>(Q, E);
    argmin_mma_kernel<<<NBLK, 256, SM_TOTAL>>>();
    rescore_kernel<<<NQ / 256, 256>>>(Q, E);
    gather_kernel<<<NQ / 4, 256>>>(Q, E, out);
    loss_kernel<<<1, 1>>>(out);
}